// round 4
// baseline (speedup 1.0000x reference)
#include <cuda_runtime.h>

// CRF negative log-likelihood on GB300.
// B=512 sequences, S=1024 steps, T=32 tags. One warp per sequence.
// Partition function via base-2 forward recursion with exp(trans) precomputed
// into registers: per step only ONE EX2 per lane + 32 shfl-broadcast FFMAs.

#define FULLMASK 0xFFFFFFFFu

__device__ __forceinline__ float ex2f(float x) {
    float r; asm("ex2.approx.ftz.f32 %0, %1;" : "=f"(r) : "f"(x)); return r;
}
__device__ __forceinline__ float lg2f(float x) {
    float r; asm("lg2.approx.ftz.f32 %0, %1;" : "=f"(r) : "f"(x)); return r;
}

__global__ void crf_zero_kernel(float* out) {
    if (threadIdx.x == 0) out[0] = 0.0f;
}

__global__ void __launch_bounds__(32) crf_main_kernel(
    const float* __restrict__ emis,     // [B, S, T]
    const int*   __restrict__ tags32,   // [B, S] int32 or int64 (detected)
    const float* __restrict__ mask,     // [B, S]
    const float* __restrict__ trans,    // [T, T]
    const float* __restrict__ startT,   // [T]
    const float* __restrict__ endT,     // [T]
    float* __restrict__ out,
    int S)
{
    constexpr int T = 32;
    constexpr float LOG2E = 1.4426950408889634f;
    constexpr float LN2   = 0.6931471805599453f;

    const int b = blockIdx.x;
    const int t = threadIdx.x;          // lane == tag index
    const long base = (long)b * S;      // offset into [B,S]

    // ---- detect int64 vs int32 tag layout (little-endian) ----
    // If tags are int64, every odd 32-bit word is 0 (values in [0,32)).
    // P(128 random tags all == 0 | int32) = 32^-128 ~ 0.
    int nz = 0;
    for (int k = t; k < 128; k += 32) nz |= tags32[2 * k + 1];
    nz = __reduce_or_sync(FULLMASK, nz);
    const bool is64 = (nz == 0);

    // ---- gold-path score + mask sum (parallel over lanes, high MLP) ----
    float sc = 0.0f, msum = 0.0f;
    for (int s = t; s < S; s += 32) {
        float mk = mask[base + s];
        msum += mk;
        if (s >= 1) {
            long ic = base + s, ip = base + s - 1;
            int tc = is64 ? tags32[2 * ic] : tags32[ic];
            int tp = is64 ? tags32[2 * ip] : tags32[ip];
            sc += (emis[ic * T + tc] + trans[tp * T + tc]) * mk;
        }
    }
    #pragma unroll
    for (int d = 16; d; d >>= 1) {
        sc   += __shfl_xor_sync(FULLMASK, sc, d);
        msum += __shfl_xor_sync(FULLMASK, msum, d);
    }

    // ---- precompute E[i] = exp(trans[i][t]) column into registers ----
    float E[32];
    #pragma unroll
    for (int i = 0; i < 32; i++)
        E[i] = ex2f(trans[i * T + t] * LOG2E);

    // ---- forward recursion in log2 domain ----
    // alpha_t = log2-domain forward variable for tag t of this sequence.
    float alpha = (startT[t] + emis[base * T + t]) * LOG2E;

    constexpr int PF = 4;               // emission/mask prefetch depth
    float ebuf[PF], mbuf[PF];
    #pragma unroll
    for (int k = 0; k < PF; k++) {
        int s = 1 + k;
        ebuf[k] = (s < S) ? emis[(base + s) * T + t] : 0.0f;
        mbuf[k] = (s < S) ? mask[base + s] : 0.0f;
    }

    #pragma unroll 4
    for (int s = 1; s < S; s++) {
        const int slot = (s - 1) & (PF - 1);
        const float e  = ebuf[slot];
        const float mk = mbuf[slot];
        const int sn = s + PF;
        if (sn < S) {                   // uniform branch
            ebuf[slot] = emis[(base + sn) * T + t];
            mbuf[slot] = mask[base + sn];
        }

        // uniform anchor (exact: m cancels in the logsumexp identity)
        const float m = __shfl_sync(FULLMASK, alpha, 0);
        const float p = ex2f(alpha - m);          // single EX2 per lane

        float a0 = 0.f, a1 = 0.f, a2 = 0.f, a3 = 0.f;
        #pragma unroll
        for (int i = 0; i < 32; i += 4) {
            float p0 = __shfl_sync(FULLMASK, p, i);
            float p1 = __shfl_sync(FULLMASK, p, i + 1);
            float p2 = __shfl_sync(FULLMASK, p, i + 2);
            float p3 = __shfl_sync(FULLMASK, p, i + 3);
            a0 = fmaf(p0, E[i],     a0);
            a1 = fmaf(p1, E[i + 1], a1);
            a2 = fmaf(p2, E[i + 2], a2);
            a3 = fmaf(p3, E[i + 3], a3);
        }
        const float sum  = (a0 + a1) + (a2 + a3);  // > 0 always (p at max lane >= 1)
        const float anew = fmaf(e, LOG2E, m + lg2f(sum));
        alpha = (mk != 0.0f) ? anew : alpha;       // mask blend (select, no branch)
    }

    // ---- final logsumexp over tags (+ end transitions), back to natural log ----
    float av = fmaf(endT[t], LOG2E, alpha);
    float mm = av;
    #pragma unroll
    for (int d = 16; d; d >>= 1) mm = fmaxf(mm, __shfl_xor_sync(FULLMASK, mm, d));
    float se = ex2f(av - mm);
    #pragma unroll
    for (int d = 16; d; d >>= 1) se += __shfl_xor_sync(FULLMASK, se, d);
    const float partition = (mm + lg2f(se)) * LN2;

    if (t == 0) {
        const int last = (int)(msum + 0.5f) - 1;
        long i0 = base, il = base + last;
        int tg0 = is64 ? tags32[2 * i0] : tags32[i0];
        int tgl = is64 ? tags32[2 * il] : tags32[il];
        const float score = sc + startT[tg0] + emis[i0 * T + tg0] + endT[tgl];
        atomicAdd(out, partition - score);         // out = sum(partition - score)
    }
}

extern "C" void kernel_launch(void* const* d_in, const int* in_sizes, int n_in,
                              void* d_out, int out_size) {
    const float* emis   = (const float*)d_in[0];   // [B,S,T] float32
    const int*   tags   = (const int*)  d_in[1];   // [B,S] int (32 or 64, detected)
    const float* mask   = (const float*)d_in[2];   // [B,S] float32
    const float* trans  = (const float*)d_in[3];   // [T,T]
    const float* startT = (const float*)d_in[4];   // [T]
    const float* endT   = (const float*)d_in[5];   // [T]
    float* out = (float*)d_out;

    const int S  = 1024;                           // fixed problem shape
    const int BS = in_sizes[2];                    // mask element count = B*S
    const int B  = BS / S;

    crf_zero_kernel<<<1, 32>>>(out);
    crf_main_kernel<<<B, 32>>>(emis, tags, mask, trans, startT, endT, out, S);
}

// round 6
// speedup vs baseline: 2.1286x; 2.1286x over previous
#include <cuda_runtime.h>
#include <cstdint>

// CRF negative log-likelihood on GB300 (sm_103a).
// B=512 sequences, S=1024 steps, T=32 tags. One warp per sequence.
// LINEAR-domain forward recursion: a' = (E^T a) * 2^(e*log2e) * scale, with
//  - E = exp(trans) pre-packed as f32x2 pairs in registers,
//  - a broadcast via SMEM (STS + BAR @nw=1 + 8x LDS.128), volatile + memory
//    clobber (R5 bug: non-volatile asm was CSE'd across steps -> stale data),
//  - emission exp2 computed at prefetch time (PF=8, off the serial chain),
//  - every-step uniform exponent rescale folded into pe (off-chain shfl+bitops).

#define FULLMASK 0xFFFFFFFFu

__device__ __forceinline__ float ex2f(float x) {
    float r; asm("ex2.approx.ftz.f32 %0, %1;" : "=f"(r) : "f"(x)); return r;
}
__device__ __forceinline__ float lg2f(float x) {
    float r; asm("lg2.approx.ftz.f32 %0, %1;" : "=f"(r) : "f"(x)); return r;
}
__device__ __forceinline__ unsigned long long packf2(float lo, float hi) {
    unsigned long long d; asm("mov.b64 %0, {%1, %2};" : "=l"(d) : "f"(lo), "f"(hi)); return d;
}
__device__ __forceinline__ void unpackf2(unsigned long long d, float& lo, float& hi) {
    asm("mov.b64 {%0, %1}, %2;" : "=f"(lo), "=f"(hi) : "l"(d));
}
__device__ __forceinline__ unsigned long long fma2(unsigned long long a,
                                                   unsigned long long b,
                                                   unsigned long long c) {
    unsigned long long d;
    asm("fma.rn.f32x2 %0, %1, %2, %3;" : "=l"(d) : "l"(a), "l"(b), "l"(c));
    return d;
}
__device__ __forceinline__ unsigned long long add2(unsigned long long a,
                                                   unsigned long long b) {
    unsigned long long d;
    asm("add.rn.f32x2 %0, %1, %2;" : "=l"(d) : "l"(a), "l"(b));
    return d;
}

__global__ void crf_zero_kernel(float* out) {
    if (threadIdx.x == 0) out[0] = 0.0f;
}

__global__ void __launch_bounds__(32) crf_main_kernel(
    const float* __restrict__ emis,     // [B, S, T]
    const int*   __restrict__ tags32,   // [B, S] int32 or int64 (detected)
    const float* __restrict__ mask,     // [B, S]
    const float* __restrict__ trans,    // [T, T]
    const float* __restrict__ startT,   // [T]
    const float* __restrict__ endT,     // [T]
    float* __restrict__ out,
    int S)
{
    constexpr int T = 32;
    constexpr float LOG2E = 1.4426950408889634f;
    constexpr float LN2   = 0.6931471805599453f;
    constexpr int PF = 8;               // emission prefetch depth (> 577cyc/step)

    __shared__ __align__(16) float pbuf[64];   // double-buffered broadcast slab

    const int b = blockIdx.x;
    const int t = threadIdx.x;          // lane == tag index
    const long base = (long)b * S;

    // ---- detect int64 vs int32 tag layout (little-endian) ----
    int nz = 0;
    for (int k = t; k < 128; k += 32) nz |= tags32[2 * k + 1];
    nz = __reduce_or_sync(FULLMASK, nz);
    const bool is64 = (nz == 0);

    // ---- gold-path score + mask sum (parallel over lanes, high MLP) ----
    float sc = 0.0f, msum = 0.0f;
    #pragma unroll 4
    for (int s = t; s < S; s += 32) {
        float mk = mask[base + s];
        msum += mk;
        if (s >= 1) {
            long ic = base + s, ip = base + s - 1;
            int tc = is64 ? tags32[2 * ic] : tags32[ic];
            int tp = is64 ? tags32[2 * ip] : tags32[ip];
            sc += (emis[ic * T + tc] + trans[tp * T + tc]) * mk;
        }
    }
    #pragma unroll
    for (int d = 16; d; d >>= 1) {
        sc   += __shfl_xor_sync(FULLMASK, sc, d);
        msum += __shfl_xor_sync(FULLMASK, msum, d);
    }

    // ---- E column for this lane, packed f32x2: E2[j] = (E[2j][t], E[2j+1][t])
    unsigned long long E2[16];
    #pragma unroll
    for (int j = 0; j < 16; j++) {
        float lo = ex2f(trans[(2 * j)     * T + t] * LOG2E);
        float hi = ex2f(trans[(2 * j + 1) * T + t] * LOG2E);
        E2[j] = packf2(lo, hi);
    }

    // ---- init: a_t = 2^(al0 - C), C = lane0 anchor (log2 offset, uniform) ----
    float al0 = (startT[t] + emis[base * T + t]) * LOG2E;
    float C   = __shfl_sync(FULLMASK, al0, 0);
    float a   = ex2f(al0 - C);

    // ---- prefetch: emission exp2 + mask, PF deep (EX2 off the serial chain) ----
    float pebuf[PF], mbuf[PF];
    #pragma unroll
    for (int k = 0; k < PF; k++) {
        int s  = 1 + k;
        int sp = (s < S) ? s : (S - 1);
        pebuf[k] = ex2f(emis[(base + sp) * T + t] * LOG2E);
        mbuf[k]  = mask[base + sp];
    }

    const uint32_t sbase = (uint32_t)__cvta_generic_to_shared(pbuf);

    // One recursion step. slot is always a compile-time constant.
    auto step = [&](int s, int slot, bool do_prefetch) {
        const float pe = pebuf[slot];             // 2^(e_s * log2e), precomputed
        const float mk = mbuf[slot];
        if (do_prefetch) {
            const int sn = s + PF;
            const int sp = (sn < S) ? sn : (S - 1);
            pebuf[slot] = ex2f(emis[(base + sp) * T + t] * LOG2E);
            mbuf[slot]  = mask[base + sp];
        }

        // Uniform rescale anchor: shfl issues at step top; 26cyc latency runs
        // in parallel with STS+BAR+LDS below. All derived ops are off-chain.
        const float m0 = __shfl_sync(FULLMASK, a, 0);
        unsigned ex = (__float_as_uint(m0) >> 23) & 0xFFu;
        ex = (ex < 1u) ? 1u : ((ex > 253u) ? 253u : ex);
        const float scale = __uint_as_float((254u - ex) << 23);  // 2^(127-ex)
        C += (float)((int)ex - 127);
        const float pes = pe * scale;
        const float asc = a * scale;

        // ---- broadcast a via SMEM (double-buffered, one BAR per step) ----
        const uint32_t off = sbase + ((s & 1) << 7);   // 128B per buffer
        pbuf[((s & 1) << 5) + t] = a;
        __syncthreads();                               // BAR @nw=1, drains STS

        // ---- y_t = sum_i a_i * E[i][t]: 8x LDS.128 broadcast + 16x FFMA2 ----
        // volatile + "memory": these MUST re-read SMEM every step (R5 bug).
        unsigned long long acc0 = 0ull, acc1 = 0ull, acc2 = 0ull, acc3 = 0ull;
        #pragma unroll
        for (int j = 0; j < 4; j++) {
            unsigned long long q0, q1, q2, q3;
            asm volatile("ld.shared.v2.u64 {%0, %1}, [%2];"
                : "=l"(q0), "=l"(q1) : "r"(off + 32u * j) : "memory");
            asm volatile("ld.shared.v2.u64 {%0, %1}, [%2 + 16];"
                : "=l"(q2), "=l"(q3) : "r"(off + 32u * j) : "memory");
            acc0 = fma2(q0, E2[4 * j + 0], acc0);
            acc1 = fma2(q1, E2[4 * j + 1], acc1);
            acc2 = fma2(q2, E2[4 * j + 2], acc2);
            acc3 = fma2(q3, E2[4 * j + 3], acc3);
        }
        acc0 = add2(acc0, acc1);
        acc2 = add2(acc2, acc3);
        acc0 = add2(acc0, acc2);
        float lo, hi; unpackf2(acc0, lo, hi);
        const float y = (lo + hi) * pes;          // sum > 0 always

        a = fmaf(mk, y - asc, asc);               // mask blend (mk in {0,1})
    };

    // Blocked loop: (S-1) = 1023 = 127 * 8 + 7; all slot indices static.
    int s = 1;
    for (int blk = 0; blk < (S - 1) / PF; blk++) {
        #pragma unroll
        for (int u = 0; u < PF; u++, s++) step(s, u, true);
    }
    #pragma unroll
    for (int u = 0; u < (S - 1) % PF; u++, s++) step(s, u, false);

    // ---- final: partition = (C + log2(sum_t a_t * 2^(endT*log2e))) * ln2 ----
    float av = a * ex2f(endT[t] * LOG2E);
    float se = av;
    #pragma unroll
    for (int d = 16; d; d >>= 1) se += __shfl_xor_sync(FULLMASK, se, d);
    const float partition = (C + lg2f(se)) * LN2;

    if (t == 0) {
        const int last = (int)(msum + 0.5f) - 1;
        long i0 = base, il = base + last;
        int tg0 = is64 ? tags32[2 * i0] : tags32[i0];
        int tgl = is64 ? tags32[2 * il] : tags32[il];
        const float score = sc + startT[tg0] + emis[i0 * T + tg0] + endT[tgl];
        atomicAdd(out, partition - score);        // out = sum(partition - score)
    }
}

extern "C" void kernel_launch(void* const* d_in, const int* in_sizes, int n_in,
                              void* d_out, int out_size) {
    const float* emis   = (const float*)d_in[0];   // [B,S,T] float32
    const int*   tags   = (const int*)  d_in[1];   // [B,S] int (32/64 detected)
    const float* mask   = (const float*)d_in[2];   // [B,S] float32
    const float* trans  = (const float*)d_in[3];   // [T,T]
    const float* startT = (const float*)d_in[4];   // [T]
    const float* endT   = (const float*)d_in[5];   // [T]
    float* out = (float*)d_out;

    const int S  = 1024;
    const int BS = in_sizes[2];                    // mask element count = B*S
    const int B  = BS / S;

    crf_zero_kernel<<<1, 32>>>(out);
    crf_main_kernel<<<B, 32>>>(emis, tags, mask, trans, startT, endT, out, S);
}

// round 8
// speedup vs baseline: 2.4040x; 1.1294x over previous
#include <cuda_runtime.h>
#include <cstdint>

// CRF negative log-likelihood on GB300 (sm_103a).
// B=512 sequences, S=1024 steps, T=32 tags. One warp per sequence.
// LINEAR-domain forward recursion: a' = (E^T a) * 2^(e*log2e) * scale.
//  - E = exp(trans) pre-packed as f32x2 pairs in registers,
//  - a broadcast via SMEM (STS + BAR @nw=1 + 8x LDS.128, volatile+memory),
//  - R6 fix: prefetch buffers hold RAW emission/mask (LDG consumed 8 steps
//    later, > DRAM latency); EX2 conversion happens at step top where it is
//    hidden under the broadcast round — previously EX2 sat on its own LDG
//    and stalled ~150+ cyc/step on long_scoreboard.
//  - every-step uniform exponent rescale folded into pe (off-chain).

#define FULLMASK 0xFFFFFFFFu

__device__ __forceinline__ float ex2f(float x) {
    float r; asm("ex2.approx.ftz.f32 %0, %1;" : "=f"(r) : "f"(x)); return r;
}
__device__ __forceinline__ float lg2f(float x) {
    float r; asm("lg2.approx.ftz.f32 %0, %1;" : "=f"(r) : "f"(x)); return r;
}
__device__ __forceinline__ unsigned long long packf2(float lo, float hi) {
    unsigned long long d; asm("mov.b64 %0, {%1, %2};" : "=l"(d) : "f"(lo), "f"(hi)); return d;
}
__device__ __forceinline__ void unpackf2(unsigned long long d, float& lo, float& hi) {
    asm("mov.b64 {%0, %1}, %2;" : "=f"(lo), "=f"(hi) : "l"(d));
}
__device__ __forceinline__ unsigned long long fma2(unsigned long long a,
                                                   unsigned long long b,
                                                   unsigned long long c) {
    unsigned long long d;
    asm("fma.rn.f32x2 %0, %1, %2, %3;" : "=l"(d) : "l"(a), "l"(b), "l"(c));
    return d;
}
__device__ __forceinline__ unsigned long long add2(unsigned long long a,
                                                   unsigned long long b) {
    unsigned long long d;
    asm("add.rn.f32x2 %0, %1, %2;" : "=l"(d) : "l"(a), "l"(b));
    return d;
}

__global__ void crf_zero_kernel(float* out) {
    if (threadIdx.x == 0) out[0] = 0.0f;
}

__global__ void __launch_bounds__(32) crf_main_kernel(
    const float* __restrict__ emis,     // [B, S, T]
    const int*   __restrict__ tags32,   // [B, S] int32 or int64 (detected)
    const float* __restrict__ mask,     // [B, S]
    const float* __restrict__ trans,    // [T, T]
    const float* __restrict__ startT,   // [T]
    const float* __restrict__ endT,     // [T]
    float* __restrict__ out,
    int S)
{
    constexpr int T = 32;
    constexpr float LOG2E = 1.4426950408889634f;
    constexpr float LN2   = 0.6931471805599453f;
    constexpr int PF = 8;               // raw-prefetch depth: 8 steps > DRAM lat

    __shared__ __align__(16) float pbuf[64];   // double-buffered broadcast slab

    const int b = blockIdx.x;
    const int t = threadIdx.x;          // lane == tag index
    const long base = (long)b * S;

    // ---- detect int64 vs int32 tag layout (little-endian) ----
    int nz = 0;
    for (int k = t; k < 128; k += 32) nz |= tags32[2 * k + 1];
    nz = __reduce_or_sync(FULLMASK, nz);
    const bool is64 = (nz == 0);

    // ---- gold-path score + mask sum (parallel over lanes, high MLP) ----
    float sc = 0.0f, msum = 0.0f;
    #pragma unroll 4
    for (int s = t; s < S; s += 32) {
        float mk = mask[base + s];
        msum += mk;
        if (s >= 1) {
            long ic = base + s, ip = base + s - 1;
            int tc = is64 ? tags32[2 * ic] : tags32[ic];
            int tp = is64 ? tags32[2 * ip] : tags32[ip];
            sc += (emis[ic * T + tc] + trans[tp * T + tc]) * mk;
        }
    }
    #pragma unroll
    for (int d = 16; d; d >>= 1) {
        sc   += __shfl_xor_sync(FULLMASK, sc, d);
        msum += __shfl_xor_sync(FULLMASK, msum, d);
    }

    // ---- E column for this lane, packed f32x2: E2[j] = (E[2j][t], E[2j+1][t])
    unsigned long long E2[16];
    #pragma unroll
    for (int j = 0; j < 16; j++) {
        float lo = ex2f(trans[(2 * j)     * T + t] * LOG2E);
        float hi = ex2f(trans[(2 * j + 1) * T + t] * LOG2E);
        E2[j] = packf2(lo, hi);
    }

    // ---- init: a_t = 2^(al0 - C), C = lane0 anchor (log2 offset, uniform) ----
    float al0 = (startT[t] + emis[base * T + t]) * LOG2E;
    float C   = __shfl_sync(FULLMASK, al0, 0);
    float a   = ex2f(al0 - C);

    // ---- RAW prefetch: emission + mask, PF deep (no conversion here!) ----
    float rawe[PF], rawm[PF];
    #pragma unroll
    for (int k = 0; k < PF; k++) {
        int s  = 1 + k;
        int sp = (s < S) ? s : (S - 1);
        rawe[k] = emis[(base + sp) * T + t];
        rawm[k] = mask[base + sp];
    }

    const uint32_t sbase = (uint32_t)__cvta_generic_to_shared(pbuf);

    // One recursion step. slot is always a compile-time constant.
    auto step = [&](int s, int slot, bool do_prefetch) {
        // Convert at consumption: EX2 (16cyc) runs under the broadcast round.
        const float pe = ex2f(rawe[slot] * LOG2E);
        const float mk = rawm[slot];
        if (do_prefetch) {
            const int sn = s + PF;
            const int sp = (sn < S) ? sn : (S - 1);
            rawe[slot] = emis[(base + sp) * T + t];   // consumed 8 steps later
            rawm[slot] = mask[base + sp];
        }

        // Uniform rescale anchor: shfl issues at step top; its 26cyc latency
        // runs in parallel with STS+BAR+LDS below. All derived ops off-chain.
        const float m0 = __shfl_sync(FULLMASK, a, 0);
        unsigned ex = (__float_as_uint(m0) >> 23) & 0xFFu;
        ex = (ex < 1u) ? 1u : ((ex > 253u) ? 253u : ex);
        const float scale = __uint_as_float((254u - ex) << 23);  // 2^(127-ex)
        C += (float)((int)ex - 127);
        const float pes = pe * scale;
        const float asc = a * scale;

        // ---- broadcast a via SMEM (double-buffered, one BAR per step) ----
        const uint32_t off = sbase + ((s & 1) << 7);   // 128B per buffer
        pbuf[((s & 1) << 5) + t] = a;
        __syncthreads();                               // BAR @nw=1, drains STS

        // ---- y_t = sum_i a_i * E[i][t]: 8x LDS.128 broadcast + 16x FFMA2 ----
        // volatile + "memory": must re-read SMEM every step (R5 lesson).
        unsigned long long acc0 = 0ull, acc1 = 0ull, acc2 = 0ull, acc3 = 0ull;
        #pragma unroll
        for (int j = 0; j < 4; j++) {
            unsigned long long q0, q1, q2, q3;
            asm volatile("ld.shared.v2.u64 {%0, %1}, [%2];"
                : "=l"(q0), "=l"(q1) : "r"(off + 32u * j) : "memory");
            asm volatile("ld.shared.v2.u64 {%0, %1}, [%2 + 16];"
                : "=l"(q2), "=l"(q3) : "r"(off + 32u * j) : "memory");
            acc0 = fma2(q0, E2[4 * j + 0], acc0);
            acc1 = fma2(q1, E2[4 * j + 1], acc1);
            acc2 = fma2(q2, E2[4 * j + 2], acc2);
            acc3 = fma2(q3, E2[4 * j + 3], acc3);
        }
        acc0 = add2(acc0, acc1);
        acc2 = add2(acc2, acc3);
        acc0 = add2(acc0, acc2);
        float lo, hi; unpackf2(acc0, lo, hi);
        const float y = (lo + hi) * pes;          // sum > 0 always

        a = fmaf(mk, y - asc, asc);               // mask blend (mk in {0,1})
    };

    // Blocked loop: (S-1) = 1023 = 127 * 8 + 7; all slot indices static.
    int s = 1;
    for (int blk = 0; blk < (S - 1) / PF; blk++) {
        #pragma unroll
        for (int u = 0; u < PF; u++, s++) step(s, u, true);
    }
    #pragma unroll
    for (int u = 0; u < (S - 1) % PF; u++, s++) step(s, u, false);

    // ---- final: partition = (C + log2(sum_t a_t * 2^(endT*log2e))) * ln2 ----
    float av = a * ex2f(endT[t] * LOG2E);
    float se = av;
    #pragma unroll
    for (int d = 16; d; d >>= 1) se += __shfl_xor_sync(FULLMASK, se, d);
    const float partition = (C + lg2f(se)) * LN2;

    if (t == 0) {
        const int last = (int)(msum + 0.5f) - 1;
        long i0 = base, il = base + last;
        int tg0 = is64 ? tags32[2 * i0] : tags32[i0];
        int tgl = is64 ? tags32[2 * il] : tags32[il];
        const float score = sc + startT[tg0] + emis[i0 * T + tg0] + endT[tgl];
        atomicAdd(out, partition - score);        // out = sum(partition - score)
    }
}

extern "C" void kernel_launch(void* const* d_in, const int* in_sizes, int n_in,
                              void* d_out, int out_size) {
    const float* emis   = (const float*)d_in[0];   // [B,S,T] float32
    const int*   tags   = (const int*)  d_in[1];   // [B,S] int (32/64 detected)
    const float* mask   = (const float*)d_in[2];   // [B,S] float32
    const float* trans  = (const float*)d_in[3];   // [T,T]
    const float* startT = (const float*)d_in[4];   // [T]
    const float* endT   = (const float*)d_in[5];   // [T]
    float* out = (float*)d_out;

    const int S  = 1024;
    const int BS = in_sizes[2];                    // mask element count = B*S
    const int B  = BS / S;

    crf_zero_kernel<<<1, 32>>>(out);
    crf_main_kernel<<<B, 32>>>(emis, tags, mask, trans, startT, endT, out, S);
}